// round 1
// baseline (speedup 1.0000x reference)
#include <cuda_runtime.h>
#include <math.h>
#include <stdint.h>

// ---------------- constants ----------------
#define TEMP      0.07f
#define INV_TEMP  (1.0f / 0.07f)
#define MOMENTUM  0.2f
#define KSEL      1024
#define NEPS      1e-12f

#define BM 64
#define BN 64
#define BK 32
#define LDSS 68   // smem row stride (floats): 68*4=272 bytes, 16B-aligned rows, staggers banks

// ---------------- scratch ----------------
static __device__ float g_mat[64 * 16384];   // [B][N] similarity matrix
static __device__ float g_loss[64];

// ---------------- helpers ----------------
__device__ __forceinline__ void fma2(unsigned long long &d, unsigned long long a, unsigned long long b) {
    asm("fma.rn.f32x2 %0, %1, %2, %0;" : "+l"(d) : "l"(a), "l"(b));
}
__device__ __forceinline__ unsigned long long splat2(float x) {
    unsigned long long r;
    asm("mov.b64 %0, {%1, %1};" : "=l"(r) : "f"(x));
    return r;
}
__device__ __forceinline__ float keyval(unsigned k) {
    unsigned u = (k & 0x80000000u) ? (k & 0x7fffffffu) : ~k;
    return __uint_as_float(u);
}

// ---------------- GEMM (64 x N x D) fused with features->out copy ----------------
// grid.x = N/BN, 256 threads, micro-tile 4(b) x 4(n) per thread via packed f32x2 FMA.
extern "C" __global__ void __launch_bounds__(256, 2)
gemm_copy_kernel(const float* __restrict__ f, const float* __restrict__ feat,
                 float* __restrict__ outF, int N, int D)
{
    __shared__ float As[BK * LDSS];
    __shared__ float Bs[BK * LDSS];

    const int tid = threadIdx.x;
    const int tx  = tid & 15;     // n direction
    const int ty  = tid >> 4;     // b direction
    const int n0  = blockIdx.x * BN;
    const int nK  = D / BK;

    unsigned long long acc[4][2];
#pragma unroll
    for (int i = 0; i < 4; i++) { acc[i][0] = 0ull; acc[i][1] = 0ull; }

    // loader mapping: per thread two (row, kq) entries; 8 lanes cover 128B of a row
    const int r0 = tid >> 3;      // 0..31
    const int kq = tid & 7;       // 0..7

    const float* fA0 = f    + (size_t)r0        * D + kq * 4;
    const float* fA1 = f    + (size_t)(r0 + 32) * D + kq * 4;
    const float* fB0 = feat + (size_t)(n0 + r0)      * D + kq * 4;
    const float* fB1 = feat + (size_t)(n0 + r0 + 32) * D + kq * 4;

    float4 ra0 = *(const float4*)fA0;
    float4 ra1 = *(const float4*)fA1;
    float4 rb0 = *(const float4*)fB0;
    float4 rb1 = *(const float4*)fB1;

    for (int kt = 0; kt < nK; kt++) {
        // stage current tile into smem (K-major), and stream B tile to output (copy fusion)
        {
            int c0 = kq * 4;
            As[(c0 + 0) * LDSS + r0] = ra0.x;
            As[(c0 + 1) * LDSS + r0] = ra0.y;
            As[(c0 + 2) * LDSS + r0] = ra0.z;
            As[(c0 + 3) * LDSS + r0] = ra0.w;
            As[(c0 + 0) * LDSS + r0 + 32] = ra1.x;
            As[(c0 + 1) * LDSS + r0 + 32] = ra1.y;
            As[(c0 + 2) * LDSS + r0 + 32] = ra1.z;
            As[(c0 + 3) * LDSS + r0 + 32] = ra1.w;

            Bs[(c0 + 0) * LDSS + r0] = rb0.x;
            Bs[(c0 + 1) * LDSS + r0] = rb0.y;
            Bs[(c0 + 2) * LDSS + r0] = rb0.z;
            Bs[(c0 + 3) * LDSS + r0] = rb0.w;
            Bs[(c0 + 0) * LDSS + r0 + 32] = rb1.x;
            Bs[(c0 + 1) * LDSS + r0 + 32] = rb1.y;
            Bs[(c0 + 2) * LDSS + r0 + 32] = rb1.z;
            Bs[(c0 + 3) * LDSS + r0 + 32] = rb1.w;

            size_t o0 = (size_t)(n0 + r0)      * D + (size_t)kt * BK + c0;
            size_t o1 = (size_t)(n0 + r0 + 32) * D + (size_t)kt * BK + c0;
            outF[o0 + 0] = rb0.x; outF[o0 + 1] = rb0.y; outF[o0 + 2] = rb0.z; outF[o0 + 3] = rb0.w;
            outF[o1 + 0] = rb1.x; outF[o1 + 1] = rb1.y; outF[o1 + 2] = rb1.z; outF[o1 + 3] = rb1.w;
        }
        __syncthreads();

        // prefetch next tile into registers (hidden under compute)
        if (kt + 1 < nK) {
            int off = (kt + 1) * BK;
            ra0 = *(const float4*)(fA0 + off);
            ra1 = *(const float4*)(fA1 + off);
            rb0 = *(const float4*)(fB0 + off);
            rb1 = *(const float4*)(fB1 + off);
        }

#pragma unroll
        for (int kk = 0; kk < BK; kk++) {
            float4 a4 = *(const float4*)&As[kk * LDSS + ty * 4];
            float4 b4 = *(const float4*)&Bs[kk * LDSS + tx * 4];
            unsigned long long bp0 = *reinterpret_cast<unsigned long long*>(&b4.x);
            unsigned long long bp1 = *reinterpret_cast<unsigned long long*>(&b4.z);
            unsigned long long s0 = splat2(a4.x);
            unsigned long long s1 = splat2(a4.y);
            unsigned long long s2 = splat2(a4.z);
            unsigned long long s3 = splat2(a4.w);
            fma2(acc[0][0], s0, bp0); fma2(acc[0][1], s0, bp1);
            fma2(acc[1][0], s1, bp0); fma2(acc[1][1], s1, bp1);
            fma2(acc[2][0], s2, bp0); fma2(acc[2][1], s2, bp1);
            fma2(acc[3][0], s3, bp0); fma2(acc[3][1], s3, bp1);
        }
        __syncthreads();
    }

    // write C tile: mat[b][n]
#pragma unroll
    for (int i = 0; i < 4; i++) {
        int b = ty * 4 + i;
        float c00, c01, c10, c11;
        asm("mov.b64 {%0,%1}, %2;" : "=f"(c00), "=f"(c01) : "l"(acc[i][0]));
        asm("mov.b64 {%0,%1}, %2;" : "=f"(c10), "=f"(c11) : "l"(acc[i][1]));
        float4 v = make_float4(c00, c01, c10, c11);
        *(float4*)(g_mat + (size_t)b * N + n0 + tx * 4) = v;
    }
}

// ---------------- per-row exact top-K (radix select) + loss ----------------
// one block per batch row b; keys for the whole row live in dynamic smem (N*4 bytes)
extern "C" __global__ void __launch_bounds__(256)
topk_loss_kernel(const int* __restrict__ indexes, const int* __restrict__ labels, int N)
{
    extern __shared__ unsigned skeys[];
    __shared__ unsigned hist[256];
    __shared__ float sred[256];
    __shared__ int   s_sel, s_kleft;
    __shared__ float s_pmin, s_nmax;

    const int b   = blockIdx.x;
    const int tid = threadIdx.x;
    const int mylab = labels[indexes[b]];
    const float* row = g_mat + (size_t)b * N;

    // pass 0: build monotonic keys (pos entries -> key 0), reduce pos_min / neg_max
    float pmin = INFINITY, nmax = -INFINITY;
    for (int n = tid; n < N; n += 256) {
        float s = row[n];
        unsigned u = __float_as_uint(s);
        unsigned key = (u & 0x80000000u) ? ~u : (u | 0x80000000u);
        if (labels[n] == mylab) { key = 0u; pmin = fminf(pmin, s); }
        else                    { nmax = fmaxf(nmax, s); }
        skeys[n] = key;
    }

    sred[tid] = pmin; __syncthreads();
#pragma unroll
    for (int off = 128; off > 0; off >>= 1) {
        if (tid < off) sred[tid] = fminf(sred[tid], sred[tid + off]);
        __syncthreads();
    }
    if (tid == 0) s_pmin = sred[0];
    __syncthreads();

    sred[tid] = nmax; __syncthreads();
#pragma unroll
    for (int off = 128; off > 0; off >>= 1) {
        if (tid < off) sred[tid] = fmaxf(sred[tid], sred[tid + off]);
        __syncthreads();
    }
    if (tid == 0) s_nmax = sred[0];
    __syncthreads();

    // 4-pass radix select (MSB -> LSB) for the K-th largest key
    unsigned prefix = 0, pmask = 0;
    int kwant = KSEL;
    for (int pass = 0; pass < 4; pass++) {
        const int shift = 24 - pass * 8;
        hist[tid] = 0u;
        __syncthreads();
        for (int n = tid; n < N; n += 256) {
            unsigned k = skeys[n];
            if ((k & pmask) == prefix) atomicAdd(&hist[(k >> shift) & 255u], 1u);
        }
        __syncthreads();
        if (tid == 0) {
            int cum = 0, sel = 0;
            for (int bin = 255; bin >= 0; bin--) {
                int c = (int)hist[bin];
                if (cum + c >= kwant) { sel = bin; break; }
                cum += c;
            }
            s_sel = sel; s_kleft = kwant - cum;
        }
        __syncthreads();
        prefix |= ((unsigned)s_sel) << shift;
        pmask  |= (255u << shift);
        kwant = s_kleft;
        __syncthreads();
    }
    const unsigned T = prefix;       // exact key of the K-th largest negative
    const float m = fmaxf(s_nmax, s_pmin);

    // final pass: sum exp over strict top (key > T), count them; ties filled with thresh value
    float lsum = 0.f;
    unsigned cnt = 0;
    for (int n = tid; n < N; n += 256) {
        unsigned k = skeys[n];
        if (k > T) {
            float s = keyval(k);
            lsum += __expf((s - m) * INV_TEMP);
            cnt++;
        }
    }
    sred[tid] = lsum;
    hist[tid] = cnt;
    __syncthreads();
#pragma unroll
    for (int off = 128; off > 0; off >>= 1) {
        if (tid < off) { sred[tid] += sred[tid + off]; hist[tid] += hist[tid + off]; }
        __syncthreads();
    }
    if (tid == 0) {
        float sT  = keyval(T);
        float tot = sred[0]
                  + (float)(KSEL - (int)hist[0]) * __expf((sT - m) * INV_TEMP)
                  + __expf((s_pmin - m) * INV_TEMP);
        // loss_b = logsumexp(logits) - logits[0]
        g_loss[b] = (logf(tot) + m * INV_TEMP) - s_pmin * INV_TEMP;
    }
}

// ---------------- momentum memory update (last-occurrence wins) ----------------
extern "C" __global__ void __launch_bounds__(256)
update_kernel(const float* __restrict__ feat, const float* __restrict__ f_weak,
              const int* __restrict__ indexes, float* __restrict__ outF, int B, int D)
{
    const int b   = blockIdx.x;
    const int tid = threadIdx.x;
    const int idx = indexes[b];
    bool last = true;
    for (int j = b + 1; j < B; j++) if (indexes[j] == idx) last = false;

    const float* fr = feat   + (size_t)idx * D;
    const float* fw = f_weak + (size_t)b   * D;
    __shared__ float sred[256];

    float ss = 0.f;
    for (int d = tid; d < D; d += 256) {
        float w = fr[d] * MOMENTUM + fw[d] * (1.0f - MOMENTUM);
        ss += w * w;
    }
    sred[tid] = ss; __syncthreads();
#pragma unroll
    for (int off = 128; off > 0; off >>= 1) {
        if (tid < off) sred[tid] += sred[tid + off];
        __syncthreads();
    }
    const float inv = 1.0f / fmaxf(sqrtf(sred[0]), NEPS);

    if (last) {
        float* dst = outF + (size_t)idx * D;
        for (int d = tid; d < D; d += 256) {
            float w = fr[d] * MOMENTUM + fw[d] * (1.0f - MOMENTUM);
            dst[d] = w * inv;
        }
    }
}

// ---------------- final loss reduction ----------------
extern "C" __global__ void finalize_kernel(float* __restrict__ out, int B)
{
    if (threadIdx.x == 0) {
        float t = 0.f;
        for (int i = 0; i < B; i++) t += g_loss[i];
        out[0] = t / (float)B;
    }
}

// ---------------- launch ----------------
extern "C" void kernel_launch(void* const* d_in, const int* in_sizes, int n_in,
                              void* d_out, int out_size)
{
    const float* f      = (const float*)d_in[0];
    const float* f_weak = (const float*)d_in[1];
    const int*   idx    = (const int*)  d_in[2];
    const float* feat   = (const float*)d_in[3];
    const int*   labels = (const int*)  d_in[4];

    const int B = in_sizes[2];               // 64
    const int D = in_sizes[0] / B;           // 2048
    const int N = in_sizes[4];               // 16384

    float* out  = (float*)d_out;
    float* outF = out + 1;                   // [loss, updated_features...]

    gemm_copy_kernel<<<N / BN, 256>>>(f, feat, outF, N, D);
    update_kernel<<<B, 256>>>(feat, f_weak, idx, outF, B, D);

    cudaFuncSetAttribute(topk_loss_kernel,
                         cudaFuncAttributeMaxDynamicSharedMemorySize,
                         N * (int)sizeof(unsigned));
    topk_loss_kernel<<<B, 256, (size_t)N * sizeof(unsigned)>>>(idx, labels, N);

    finalize_kernel<<<1, 32>>>(out, B);
}

// round 4
// speedup vs baseline: 1.1169x; 1.1169x over previous
#include <cuda_runtime.h>
#include <math.h>
#include <stdint.h>

// ---------------- constants ----------------
#define TEMP      0.07f
#define INV_TEMP  (1.0f / 0.07f)
#define MOMENTUM  0.2f
#define KSEL      1024
#define NEPS      1e-12f

#define GB 64
#define GN 16384
#define GD 2048

#define BM 64
#define BN 64
#define BK 32
#define LDSS 68   // smem row stride (floats)

#define TPK_THREADS 512
#define CAP 8192

// dynamic smem layout for topk kernel
#define OFF_KEYS  0
#define OFF_CAND0 65536
#define OFF_CAND1 (65536 + 32768)
#define OFF_WHIST (65536 + 65536)
#define TPK_SMEM  (OFF_WHIST + 16384)

// ---------------- scratch ----------------
static __device__ float g_mat[GB * GN];   // [B][N] similarity matrix
static __device__ float g_loss[GB];
static __device__ unsigned g_cnt = 0;

// ---------------- helpers ----------------
__device__ __forceinline__ void fma2(unsigned long long &d, unsigned long long a, unsigned long long b) {
    asm("fma.rn.f32x2 %0, %1, %2, %0;" : "+l"(d) : "l"(a), "l"(b));
}
__device__ __forceinline__ unsigned long long splat2(float x) {
    unsigned long long r;
    asm("mov.b64 %0, {%1, %1};" : "=l"(r) : "f"(x));
    return r;
}
__device__ __forceinline__ float keyval(unsigned k) {
    unsigned u = (k & 0x80000000u) ? (k & 0x7fffffffu) : ~k;
    return __uint_as_float(u);
}
__device__ __forceinline__ float wred_add(float v) {
#pragma unroll
    for (int o = 16; o > 0; o >>= 1) v += __shfl_xor_sync(0xffffffffu, v, o);
    return v;
}
__device__ __forceinline__ float wred_min(float v) {
#pragma unroll
    for (int o = 16; o > 0; o >>= 1) v = fminf(v, __shfl_xor_sync(0xffffffffu, v, o));
    return v;
}
__device__ __forceinline__ float wred_max(float v) {
#pragma unroll
    for (int o = 16; o > 0; o >>= 1) v = fmaxf(v, __shfl_xor_sync(0xffffffffu, v, o));
    return v;
}

// ---------------- GEMM (64 x N x D) fused with features->out copy (R1, proven) ----------------
extern "C" __global__ void __launch_bounds__(256, 2)
gemm_copy_kernel(const float* __restrict__ f, const float* __restrict__ feat,
                 float* __restrict__ outF, int N, int D)
{
    __shared__ float As[BK * LDSS];
    __shared__ float Bs[BK * LDSS];

    const int tid = threadIdx.x;
    const int tx  = tid & 15;
    const int ty  = tid >> 4;
    const int n0  = blockIdx.x * BN;
    const int nK  = D / BK;

    unsigned long long acc[4][2];
#pragma unroll
    for (int i = 0; i < 4; i++) { acc[i][0] = 0ull; acc[i][1] = 0ull; }

    const int r0 = tid >> 3;
    const int kq = tid & 7;

    const float* fA0 = f    + (size_t)r0        * D + kq * 4;
    const float* fA1 = f    + (size_t)(r0 + 32) * D + kq * 4;
    const float* fB0 = feat + (size_t)(n0 + r0)      * D + kq * 4;
    const float* fB1 = feat + (size_t)(n0 + r0 + 32) * D + kq * 4;

    float4 ra0 = *(const float4*)fA0;
    float4 ra1 = *(const float4*)fA1;
    float4 rb0 = *(const float4*)fB0;
    float4 rb1 = *(const float4*)fB1;

    for (int kt = 0; kt < nK; kt++) {
        {
            int c0 = kq * 4;
            As[(c0 + 0) * LDSS + r0] = ra0.x;
            As[(c0 + 1) * LDSS + r0] = ra0.y;
            As[(c0 + 2) * LDSS + r0] = ra0.z;
            As[(c0 + 3) * LDSS + r0] = ra0.w;
            As[(c0 + 0) * LDSS + r0 + 32] = ra1.x;
            As[(c0 + 1) * LDSS + r0 + 32] = ra1.y;
            As[(c0 + 2) * LDSS + r0 + 32] = ra1.z;
            As[(c0 + 3) * LDSS + r0 + 32] = ra1.w;

            Bs[(c0 + 0) * LDSS + r0] = rb0.x;
            Bs[(c0 + 1) * LDSS + r0] = rb0.y;
            Bs[(c0 + 2) * LDSS + r0] = rb0.z;
            Bs[(c0 + 3) * LDSS + r0] = rb0.w;
            Bs[(c0 + 0) * LDSS + r0 + 32] = rb1.x;
            Bs[(c0 + 1) * LDSS + r0 + 32] = rb1.y;
            Bs[(c0 + 2) * LDSS + r0 + 32] = rb1.z;
            Bs[(c0 + 3) * LDSS + r0 + 32] = rb1.w;

            size_t o0 = (size_t)(n0 + r0)      * D + (size_t)kt * BK + c0;
            size_t o1 = (size_t)(n0 + r0 + 32) * D + (size_t)kt * BK + c0;
            outF[o0 + 0] = rb0.x; outF[o0 + 1] = rb0.y; outF[o0 + 2] = rb0.z; outF[o0 + 3] = rb0.w;
            outF[o1 + 0] = rb1.x; outF[o1 + 1] = rb1.y; outF[o1 + 2] = rb1.z; outF[o1 + 3] = rb1.w;
        }
        __syncthreads();

        if (kt + 1 < nK) {
            int off = (kt + 1) * BK;
            ra0 = *(const float4*)(fA0 + off);
            ra1 = *(const float4*)(fA1 + off);
            rb0 = *(const float4*)(fB0 + off);
            rb1 = *(const float4*)(fB1 + off);
        }

#pragma unroll
        for (int kk = 0; kk < BK; kk++) {
            float4 a4 = *(const float4*)&As[kk * LDSS + ty * 4];
            float4 b4 = *(const float4*)&Bs[kk * LDSS + tx * 4];
            unsigned long long bp0 = *reinterpret_cast<unsigned long long*>(&b4.x);
            unsigned long long bp1 = *reinterpret_cast<unsigned long long*>(&b4.z);
            unsigned long long s0 = splat2(a4.x);
            unsigned long long s1 = splat2(a4.y);
            unsigned long long s2 = splat2(a4.z);
            unsigned long long s3 = splat2(a4.w);
            fma2(acc[0][0], s0, bp0); fma2(acc[0][1], s0, bp1);
            fma2(acc[1][0], s1, bp0); fma2(acc[1][1], s1, bp1);
            fma2(acc[2][0], s2, bp0); fma2(acc[2][1], s2, bp1);
            fma2(acc[3][0], s3, bp0); fma2(acc[3][1], s3, bp1);
        }
        __syncthreads();
    }

#pragma unroll
    for (int i = 0; i < 4; i++) {
        int b = ty * 4 + i;
        float c00, c01, c10, c11;
        asm("mov.b64 {%0,%1}, %2;" : "=f"(c00), "=f"(c01) : "l"(acc[i][0]));
        asm("mov.b64 {%0,%1}, %2;" : "=f"(c10), "=f"(c11) : "l"(acc[i][1]));
        float4 v = make_float4(c00, c01, c10, c11);
        *(float4*)(g_mat + (size_t)b * N + n0 + tx * 4) = v;
    }
}

// ---------------- fused update + exact top-K + loss ----------------
// 64 blocks x 512 threads. Per-warp histograms, deterministic compaction,
// incremental exp accumulation, last-block ordered loss reduction.
extern "C" __global__ void __launch_bounds__(TPK_THREADS)
topk_update_kernel(const int* __restrict__ indexes, const int* __restrict__ labels,
                   const float* __restrict__ feat, const float* __restrict__ f_weak,
                   float* __restrict__ out, float* __restrict__ outF)
{
    extern __shared__ char dyn[];
    unsigned* skeys = (unsigned*)(dyn + OFF_KEYS);
    unsigned* cbuf[2] = { (unsigned*)(dyn + OFF_CAND0), (unsigned*)(dyn + OFF_CAND1) };
    unsigned* whist = (unsigned*)(dyn + OFF_WHIST);   // [16][256]

    __shared__ unsigned hist[256];
    __shared__ unsigned sfA[256], sfB[256];
    __shared__ float    wpartf[16];
    __shared__ unsigned wsum[16], wbase[16];
    __shared__ int      s_sel, s_kleft, s_total, s_mode;
    __shared__ float    s_pmin, s_nmax, s_inv;

    const int b   = blockIdx.x;
    const int tid = threadIdx.x;
    const int wid = tid >> 5;
    const int lid = tid & 31;
    const int idx = indexes[b];

    // ---------- Part A: momentum update (last-occurrence wins) ----------
    {
        bool last = true;
        for (int j = b + 1; j < GB; j++) if (indexes[j] == idx) last = false;

        const float* fr = feat   + (size_t)idx * GD;
        const float* fw = f_weak + (size_t)b   * GD;
        float ss = 0.f;
        for (int d = tid; d < GD; d += TPK_THREADS) {
            float w = fr[d] * MOMENTUM + fw[d] * (1.0f - MOMENTUM);
            ss += w * w;
        }
        ss = wred_add(ss);
        if (lid == 0) wpartf[wid] = ss;
        __syncthreads();
        if (tid == 0) {
            float t = 0.f;
            for (int w = 0; w < 16; w++) t += wpartf[w];
            s_inv = 1.0f / fmaxf(sqrtf(t), NEPS);
        }
        __syncthreads();
        if (last) {
            const float inv = s_inv;
            float* dst = outF + (size_t)idx * GD;
            for (int d = tid; d < GD; d += TPK_THREADS) {
                float w = fr[d] * MOMENTUM + fw[d] * (1.0f - MOMENTUM);
                dst[d] = w * inv;
            }
        }
    }
    __syncthreads();

    // ---------- Part B: build keys, reduce pmin / nmax ----------
    const int mylab = labels[idx];
    const float* row = g_mat + (size_t)b * GN;

    float pmin = INFINITY, nmax = -INFINITY;
    for (int n = tid; n < GN; n += TPK_THREADS) {
        float s = row[n];
        unsigned u = __float_as_uint(s);
        unsigned key = (u & 0x80000000u) ? ~u : (u | 0x80000000u);
        if (labels[n] == mylab) { key = 0u; pmin = fminf(pmin, s); }
        else                    { nmax = fmaxf(nmax, s); }
        skeys[n] = key;
    }
    pmin = wred_min(pmin);
    nmax = wred_max(nmax);
    if (lid == 0) wpartf[wid] = pmin;
    __syncthreads();
    if (tid == 0) {
        float t = INFINITY;
        for (int w = 0; w < 16; w++) t = fminf(t, wpartf[w]);
        s_pmin = t;
    }
    __syncthreads();
    if (lid == 0) wpartf[wid] = nmax;
    __syncthreads();
    if (tid == 0) {
        float t = -INFINITY;
        for (int w = 0; w < 16; w++) t = fmaxf(t, wpartf[w]);
        s_nmax = t;
        s_kleft = KSEL;
        s_mode = 0;
        s_total = 0;
    }
    __syncthreads();

    const float m = fmaxf(s_nmax, s_pmin);
    float lsum = 0.f;

    unsigned prefix = 0, pmask = 0;
    int cur = 0;

    for (int p = 0; p < 4; p++) {
        const int shift = 24 - 8 * p;
        const int mode  = s_mode;         // uniform
        const int ncand = s_total;        // uniform
        const unsigned* src = cbuf[cur];

        // zero per-warp hists
        for (int i = tid; i < 16 * 256; i += TPK_THREADS) whist[i] = 0u;
        __syncthreads();

        // phase 1: histogram
        if (mode) {
            for (int i = tid; i < ncand; i += TPK_THREADS)
                atomicAdd(&whist[wid * 256 + ((src[i] >> shift) & 255u)], 1u);
        } else {
            for (int n = tid; n < GN; n += TPK_THREADS) {
                unsigned k = skeys[n];
                if ((k & pmask) == prefix)
                    atomicAdd(&whist[wid * 256 + ((k >> shift) & 255u)], 1u);
            }
        }
        __syncthreads();

        // reduce warp hists
        if (tid < 256) {
            unsigned t = 0;
#pragma unroll
            for (int w = 0; w < 16; w++) t += whist[w * 256 + tid];
            hist[tid] = t;
            sfA[tid] = t;
        }
        __syncthreads();

        // inclusive suffix sums (8 ping-pong steps)
        {
            unsigned* sA = sfA; unsigned* sB = sfB;
#pragma unroll
            for (int off = 1; off < 256; off <<= 1) {
                if (tid < 256) sB[tid] = sA[tid] + ((tid + off < 256) ? sA[tid + off] : 0u);
                __syncthreads();
                unsigned* t = sA; sA = sB; sB = t;
            }
            // 8 steps -> result back in sfA
        }

        // select bin
        {
            const int kleft = s_kleft;
            if (tid < 256) {
                unsigned ge = sfA[tid];
                unsigned gt = (tid < 255) ? sfA[tid + 1] : 0u;
                if ((int)gt < kleft && (int)ge >= kleft) {
                    s_sel = tid;
                    s_kleft = kleft - (int)gt;
                }
            }
        }
        __syncthreads();
        const unsigned sel = (unsigned)s_sel;

        // phase 2: count matches per thread (bin == sel)
        int mc = 0;
        if (mode) {
            for (int i = tid; i < ncand; i += TPK_THREADS)
                if (((src[i] >> shift) & 255u) == sel) mc++;
        } else {
            for (int n = tid; n < GN; n += TPK_THREADS) {
                unsigned k = skeys[n];
                if ((k & pmask) == prefix && ((k >> shift) & 255u) == sel) mc++;
            }
        }

        // deterministic exclusive scan over 512 thread counts
        unsigned x = (unsigned)mc;
#pragma unroll
        for (int off = 1; off < 32; off <<= 1) {
            unsigned y = __shfl_up_sync(0xffffffffu, x, off);
            if (lid >= off) x += y;
        }
        if (lid == 31) wsum[wid] = x;
        __syncthreads();
        if (wid == 0 && lid < 16) {
            unsigned t = wsum[lid];
#pragma unroll
            for (int off = 1; off < 16; off <<= 1) {
                unsigned y = __shfl_up_sync(0x0000ffffu, t, off);
                if (lid >= off) t += y;
            }
            wbase[lid] = t - wsum[lid];
            if (lid == 15) s_total = (int)t;
        }
        __syncthreads();
        unsigned myoff = wbase[wid] + (x - (unsigned)mc);
        const int total = s_total;
        const int doEmit = (p < 3) && (total <= CAP);   // uniform

        // phase 3: accumulate exp for bins > sel; emit bin == sel
        unsigned* dstc = cbuf[cur ^ 1];
        if (mode) {
            for (int i = tid; i < ncand; i += TPK_THREADS) {
                unsigned k = src[i];
                unsigned bin = (k >> shift) & 255u;
                if (bin > sel) lsum += __expf((keyval(k) - m) * INV_TEMP);
                else if (bin == sel && doEmit) dstc[myoff++] = k;
            }
        } else {
            for (int n = tid; n < GN; n += TPK_THREADS) {
                unsigned k = skeys[n];
                if ((k & pmask) != prefix) continue;
                unsigned bin = (k >> shift) & 255u;
                if (bin > sel) lsum += __expf((keyval(k) - m) * INV_TEMP);
                else if (bin == sel && doEmit) dstc[myoff++] = k;
            }
        }
        __syncthreads();

        prefix |= sel << shift;
        pmask  |= 255u << shift;
        if (doEmit) { cur ^= 1; if (tid == 0) s_mode = 1; }
        else if (tid == 0) { s_total = 0; }   // stay (or fall back to) filtered scans
        __syncthreads();
    }

    // threshold key + remaining tie copies
    const unsigned T = prefix;
    const int kleft = s_kleft;

    // block reduce lsum
    lsum = wred_add(lsum);
    if (lid == 0) wpartf[wid] = lsum;
    __syncthreads();
    if (tid == 0) {
        float tot = 0.f;
        for (int w = 0; w < 16; w++) tot += wpartf[w];
        tot += (float)kleft * __expf((keyval(T) - m) * INV_TEMP);
        tot += __expf((s_pmin - m) * INV_TEMP);
        float loss_b = (logf(tot) + m * INV_TEMP) - s_pmin * INV_TEMP;
        g_loss[b] = loss_b;
        __threadfence();
        unsigned ticket = atomicAdd(&g_cnt, 1u);
        if (ticket == gridDim.x - 1) {
            float t = 0.f;
            for (int i = 0; i < GB; i++) t += g_loss[i];   // fixed order -> deterministic
            out[0] = t / (float)GB;
            g_cnt = 0;
        }
    }
}

// ---------------- launch ----------------
extern "C" void kernel_launch(void* const* d_in, const int* in_sizes, int n_in,
                              void* d_out, int out_size)
{
    const float* f      = (const float*)d_in[0];
    const float* f_weak = (const float*)d_in[1];
    const int*   idx    = (const int*)  d_in[2];
    const float* feat   = (const float*)d_in[3];
    const int*   labels = (const int*)  d_in[4];

    const int B = in_sizes[2];               // 64
    const int D = in_sizes[0] / B;           // 2048
    const int N = in_sizes[4];               // 16384

    float* out  = (float*)d_out;
    float* outF = out + 1;                   // [loss, updated_features...]

    gemm_copy_kernel<<<N / BN, 256>>>(f, feat, outF, N, D);

    cudaFuncSetAttribute(topk_update_kernel,
                         cudaFuncAttributeMaxDynamicSharedMemorySize, TPK_SMEM);
    topk_update_kernel<<<B, TPK_THREADS, TPK_SMEM>>>(idx, labels, feat, f_weak, out, outF);
}